// round 6
// baseline (speedup 1.0000x reference)
#include <cuda_runtime.h>
#include <cuda_bf16.h>
#include <math.h>

#define MAX_B 16

#define PI_F        3.14159265358979323846f
#define INV2PI_F    0.15915494309189535f
#define TWOPI_HI    6.2831854820251465f
#define TWOPI_LO   -1.7484556000423536e-7f
#define MAGIC_RND   12582912.0f              // 1.5 * 2^23
#define INV_SQRT_2PI 0.3989422804014327f

#define SMEM_NODES  1536                     // 24 KB of float4
#define THREADS     512
#define WARPS       16
#define KS_PER_WARP 4
#define KS_PER_BLK  64                       // 16 warps x 4 k each
#define FULLM       0xFFFFFFFFu

__device__ __forceinline__ int warp_lower_bound(const int* __restrict__ a,
                                                int n, int v, int lane)
{
    int lo = 0, hi = n;
    while (hi - lo > 32) {
        int step = ((hi - lo) + 31) >> 5;
        int pidx = lo + (lane + 1) * step - 1;
        int probe = (pidx < hi) ? __ldg(a + pidx) : 2147483647;
        unsigned m = __ballot_sync(FULLM, probe < v);
        int c = __popc(m);
        lo = min(lo + c * step, hi);
        hi = min(lo + step, hi);
    }
    int idx = lo + lane;
    int probe = (idx < hi) ? __ldg(a + idx) : 2147483647;
    unsigned m = __ballot_sync(FULLM, probe < v);
    return lo + __popc(m);
}

__device__ __forceinline__ void fast_sincos_cw(float x, float* s, float* c) {
    float t    = fmaf(x, INV2PI_F, MAGIC_RND);
    float nrot = t - MAGIC_RND;
    float r    = fmaf(nrot, -TWOPI_HI, x);
    r          = fmaf(nrot, -TWOPI_LO, r);
    __sincosf(r, s, c);
}

__device__ __forceinline__ float perk_weight(const float* __restrict__ knorm2,
                                             const float* __restrict__ k0mask,
                                             const float* __restrict__ volume,
                                             int k, int b)
{
    float kn = __ldg(knorm2 + k);
    float fs = __expf(-0.5f * kn);                        // SIGMA = 1
    float kf = (__ldg(k0mask + k) > 0.0f) ? 0.0f : (1.0f / kn);
    return 4.0f * PI_F * fs * fs * kf / __ldg(volume + b);
}

__global__ void __launch_bounds__(THREADS, 2)
perk_kernel(const float* __restrict__ kvec,
            const float* __restrict__ knorm2,
            const int*   __restrict__ kbatch,
            const float* __restrict__ k0mask,
            const float* __restrict__ volume,
            const float* __restrict__ node_pos,
            const float* __restrict__ q,
            const int*   __restrict__ batch,
            float* __restrict__ out,
            int N, int K, int B)
{
    __shared__ float4 s_nodes[SMEM_NODES];
    __shared__ int    s_noff[MAX_B + 2];
    __shared__ float  s_e[KS_PER_BLK];
    __shared__ int    s_b[KS_PER_BLK];

    int tid  = threadIdx.x;
    int wid  = tid >> 5;
    int lane = tid & 31;

    if (tid < KS_PER_BLK) { s_e[tid] = 0.0f; s_b[tid] = -1; }

    int k0    = blockIdx.x * KS_PER_BLK;
    int kLast = min(k0 + KS_PER_BLK - 1, K - 1);
    int b0    = __ldg(kbatch + k0);
    int b1    = __ldg(kbatch + kLast);
    int prevb = (k0 > 0) ? __ldg(kbatch + k0 - 1) : -1;
    int span  = b1 - b0 + 2;                 // offsets b0 .. b1+1

    for (int off = wid; off < span; off += WARPS) {
        int r = warp_lower_bound(batch, N, b0 + off, lane);
        if (lane == 0) s_noff[b0 + off] = r;
    }
    __syncthreads();

    int ns  = s_noff[b0];
    int ne  = s_noff[b1 + 1];
    int cnt = ne - ns;
    bool use_smem = (cnt <= SMEM_NODES);

    if (use_smem) {
        const float* base = node_pos + 3 * ns;
        for (int i = tid; i < 3 * cnt; i += THREADS) {
            int node = i / 3;
            int comp = i - 3 * node;
            ((float*)&s_nodes[node])[comp] = __ldg(base + i);
        }
        for (int i = tid; i < cnt; i += THREADS)
            s_nodes[i].w = __ldg(q + ns + i);
    }
    __syncthreads();

    // ---- main loop: each warp handles 4 consecutive k's -------------------
    int ka = k0 + wid * KS_PER_WARP;
    if (ka < K) {
        int kmax = min(KS_PER_WARP, K - ka);
        int bfirst = __ldg(kbatch + ka);
        int blast  = __ldg(kbatch + ka + kmax - 1);

        if (kmax == KS_PER_WARP && bfirst == blast && use_smem) {
            // joint path: one node load feeds 4 k's
            int b = bfirst;
            float kx[4], ky[4], kz[4], sc[4], ss[4];
            #pragma unroll
            for (int j = 0; j < 4; j++) {
                kx[j] = __ldg(kvec + 3 * (ka + j) + 0);
                ky[j] = __ldg(kvec + 3 * (ka + j) + 1);
                kz[j] = __ldg(kvec + 3 * (ka + j) + 2);
                sc[j] = 0.0f; ss[j] = 0.0f;
            }
            int ws = s_noff[b] - ns;
            int we = s_noff[b + 1] - ns;
            for (int n = ws + lane; n < we; n += 32) {
                float4 pq = s_nodes[n];
                #pragma unroll
                for (int j = 0; j < 4; j++) {
                    float x = fmaf(kz[j], pq.z, fmaf(ky[j], pq.y, kx[j] * pq.x));
                    float s, c;
                    fast_sincos_cw(x, &s, &c);
                    sc[j] = fmaf(pq.w, c, sc[j]);
                    ss[j] = fmaf(pq.w, s, ss[j]);
                }
            }
            #pragma unroll
            for (int o = 16; o; o >>= 1) {
                #pragma unroll
                for (int j = 0; j < 4; j++) {
                    sc[j] += __shfl_xor_sync(FULLM, sc[j], o);
                    ss[j] += __shfl_xor_sync(FULLM, ss[j], o);
                }
            }
            if (lane == 0) {
                #pragma unroll
                for (int j = 0; j < 4; j++) {
                    float w = perk_weight(knorm2, k0mask, volume, ka + j, b);
                    s_e[wid * KS_PER_WARP + j] = w * (sc[j] * sc[j] + ss[j] * ss[j]);
                    s_b[wid * KS_PER_WARP + j] = b;
                }
            }
        } else {
            // general path (graph boundary inside the quad, or smem overflow)
            for (int j = 0; j < kmax; j++) {
                int k = ka + j;
                int b = __ldg(kbatch + k);
                float kx = __ldg(kvec + 3 * k + 0);
                float ky = __ldg(kvec + 3 * k + 1);
                float kz = __ldg(kvec + 3 * k + 2);
                float sc = 0.f, ss = 0.f;
                if (use_smem) {
                    int ws = s_noff[b] - ns;
                    int we = s_noff[b + 1] - ns;
                    for (int n = ws + lane; n < we; n += 32) {
                        float4 pq = s_nodes[n];
                        float x = fmaf(kz, pq.z, fmaf(ky, pq.y, kx * pq.x));
                        float s, c;
                        fast_sincos_cw(x, &s, &c);
                        sc = fmaf(pq.w, c, sc);
                        ss = fmaf(pq.w, s, ss);
                    }
                } else {
                    int ws = s_noff[b];
                    int we = s_noff[b + 1];
                    for (int n = ws + lane; n < we; n += 32) {
                        float px = __ldg(node_pos + 3 * n + 0);
                        float py = __ldg(node_pos + 3 * n + 1);
                        float pz = __ldg(node_pos + 3 * n + 2);
                        float qw = __ldg(q + n);
                        float x = fmaf(kz, pz, fmaf(ky, py, kx * px));
                        float s, c;
                        fast_sincos_cw(x, &s, &c);
                        sc = fmaf(qw, c, sc);
                        ss = fmaf(qw, s, ss);
                    }
                }
                #pragma unroll
                for (int o = 16; o; o >>= 1) {
                    sc += __shfl_xor_sync(FULLM, sc, o);
                    ss += __shfl_xor_sync(FULLM, ss, o);
                }
                if (lane == 0) {
                    float w = perk_weight(knorm2, k0mask, volume, k, b);
                    s_e[wid * KS_PER_WARP + j] = w * (sc * sc + ss * ss);
                    s_b[wid * KS_PER_WARP + j] = b;
                }
            }
        }
    }

    // ---- self-energy: block owning graph g's first k handles it ----------
    for (int g = prevb + 1 + wid; g <= b1; g += WARPS) {
        int gs, ge;
        if (g >= b0) { gs = s_noff[g]; ge = s_noff[g + 1]; }
        else {
            gs = warp_lower_bound(batch, N, g, lane);
            ge = warp_lower_bound(batch, N, g + 1, lane);
        }
        float self = 0.0f;
        if (use_smem && g >= b0) {
            for (int n = gs - ns + lane; n < ge - ns; n += 32) {
                float qv = s_nodes[n].w;
                self = fmaf(qv, qv, self);
            }
        } else {
            for (int n = gs + lane; n < ge; n += 32) {
                float qv = __ldg(q + n);
                self = fmaf(qv, qv, self);
            }
        }
        #pragma unroll
        for (int o = 16; o; o >>= 1)
            self += __shfl_xor_sync(FULLM, self, o);
        if (lane == 0)
            atomicAdd(out + g, -0.5f * self * INV_SQRT_2PI);
    }

    __syncthreads();

    // combine per-k energies into per-graph partials, one RED each
    if (tid < MAX_B) {
        int gb = b0 + tid;
        if (gb <= b1) {
            float sum = 0.0f;
            for (int j = 0; j < KS_PER_BLK; j++)
                if (s_b[j] == gb) sum += s_e[j];
            atomicAdd(out + gb, sum);
        }
    }
}

// ---------------- launch ---------------------------------------------------
extern "C" void kernel_launch(void* const* d_in, const int* in_sizes, int n_in,
                              void* d_out, int out_size)
{
    const float* k_vectors   = (const float*)d_in[0];
    const float* k_norm2     = (const float*)d_in[1];
    const int*   kbatch      = (const int*)  d_in[2];
    const float* k0_mask     = (const float*)d_in[3];
    const float* source_feat = (const float*)d_in[4];
    const float* node_pos    = (const float*)d_in[5];
    const int*   batch       = (const int*)  d_in[6];
    const float* volume      = (const float*)d_in[7];

    int K = in_sizes[2];
    int N = in_sizes[6];
    int B = in_sizes[7];
    if (B > MAX_B) B = MAX_B;

    float* out = (float*)d_out;

    cudaMemsetAsync(out, 0, out_size * sizeof(float), 0);

    int blocks = (K + KS_PER_BLK - 1) / KS_PER_BLK;
    perk_kernel<<<blocks, THREADS>>>(k_vectors, k_norm2, kbatch, k0_mask,
                                     volume, node_pos, source_feat, batch,
                                     out, N, K, B);
}